// round 12
// baseline (speedup 1.0000x reference)
#include <cuda_runtime.h>
#include <cuda_fp16.h>
#include <cstdint>

// ---------------------------------------------------------------------------
// DSDMSR multi-scale SRCNN cascade (sm_100 / compute_100 legacy mma path).
// conv1 (9x9,1->64): fp16 mma, split hi/lo activations; MSF input fused.
// conv2 (5x5,64->32): fp16 mma m16n8k16, cp.async double-buffered, 16x16 tile.
// conv3 (5x5,32->1): site-GEMM, 3-pass compensated + fp32 tap-sum.
// All conv kernels chained with PDL (programmatic dependent launch):
// weight staging overlaps the predecessor kernel's tail.
// ---------------------------------------------------------------------------

__device__ __half g_t1h[134217728];          // conv1 out, [z][H][W][64] fp16
__device__ __half g_t2hl[134217728];         // conv2 out, [z][H][W][32*(hi,lo)]
__device__ __half g_w1h[17 * 6 * 8 * 32 * 4];      // conv1 w frag-major
__device__ __half g_w2h[17 * 4 * 25 * 2 * 32 * 8]; // conv2 w frag-major
__device__ __half g_w3f[17 * 2048];                // conv3 w frag-major (hi,lo)

__device__ __forceinline__ unsigned pkh(__half a, __half b) {
    __half2 p = __halves2half2(a, b);
    return *(unsigned*)&p;
}
__device__ __forceinline__ void mma_f16(float c[4], const uint4& a,
                                        unsigned b0, unsigned b1) {
    asm volatile(
        "mma.sync.aligned.m16n8k16.row.col.f32.f16.f16.f32 "
        "{%0,%1,%2,%3}, {%4,%5,%6,%7}, {%8,%9}, {%0,%1,%2,%3};"
        : "+f"(c[0]), "+f"(c[1]), "+f"(c[2]), "+f"(c[3])
        : "r"(a.x), "r"(a.y), "r"(a.z), "r"(a.w), "r"(b0), "r"(b1));
}
__device__ __forceinline__ void st_hl(__half* p, float v) {
    __half h = __float2half_rn(v);
    __half l = __float2half_rn(v - __half2float(h));
    *(__half2*)p = __halves2half2(h, l);
}
__device__ __forceinline__ uint32_t smem_u32(const void* p) {
    uint32_t a;
    asm("{ .reg .u64 t; cvta.to.shared.u64 t, %1; cvt.u32.u64 %0, t; }"
        : "=r"(a) : "l"(p));
    return a;
}
__device__ __forceinline__ void cpa16(uint32_t s, const void* g, bool pred) {
    int sz = pred ? 16 : 0;
    asm volatile("cp.async.cg.shared.global [%0], [%1], 16, %2;"
                 :: "r"(s), "l"(g), "r"(sz) : "memory");
}
#define CP_COMMIT() asm volatile("cp.async.commit_group;" ::: "memory")
#define CP_WAIT(n)  asm volatile("cp.async.wait_group %0;" :: "n"(n) : "memory")
__device__ __forceinline__ void gdc_wait() {
    asm volatile("griddepcontrol.wait;" ::: "memory");
}
__device__ __forceinline__ void gdc_launch() {
    asm volatile("griddepcontrol.launch_dependents;");
}

// ---------------------------------------------------------------------------
// Weight prep: w1 frag-major, w2 frag-major, w3 frag-major hi/lo.
// ---------------------------------------------------------------------------
__global__ void prep_weights_kernel(const float* __restrict__ w1,
                                    const float* __restrict__ w2,
                                    const float* __restrict__ w3) {
    int idx = blockIdx.x * 256 + threadIdx.x;
    if (idx < 17 * 6 * 8 * 32) {
        int lane = idx & 31;
        int r = idx >> 5;
        int nt = r & 7; r >>= 3;
        int kc = r % 6;
        int u = r / 6;
        int g = lane >> 2, t = lane & 3;
        int oc = nt * 8 + g;
        int kt[4] = {kc * 16 + 2 * t, kc * 16 + 2 * t + 1,
                     kc * 16 + 2 * t + 8, kc * 16 + 2 * t + 9};
        __half* dst = g_w1h + (size_t)idx * 4;
#pragma unroll
        for (int q = 0; q < 4; q++)
            dst[q] = (kt[q] < 81)
                ? __float2half_rn(w1[((size_t)u * 64 + oc) * 81 + kt[q]])
                : __half(0.f);
    }
    if (idx < 17 * 4 * 25 * 2 * 32) {
        int l = idx & 31;
        int m = (idx >> 5) & 1;
        int rest = idx >> 6;
        int tap = rest % 25;
        int rest2 = rest / 25;
        int ch = rest2 & 3;
        int u = rest2 >> 2;
        int g = l >> 2, t = l & 3;
        int oc0 = m * 16 + g;
        int ic0 = ch * 16;
        __half* dst = g_w2h + (size_t)idx * 8;
#pragma unroll
        for (int q = 0; q < 8; q++) {
            int oc = oc0 + ((q >> 1) & 1) * 8;
            int ic = ic0 + 2 * t + (q & 1) + (q >> 2) * 8;
            dst[q] = __float2half_rn(w2[((size_t)(u * 32 + oc) * 64 + ic) * 25 + tap]);
        }
    }
    if (idx < 17 * 2 * 4 * 2 * 32) {
        int lane = idx & 31;
        int r = idx >> 5;
        int ks = r & 1; r >>= 1;
        int nt = r & 3; r >>= 2;
        int hl = r & 1; r >>= 1;
        int u = r;
        int g = lane >> 2, t = lane & 3;
        int tap = nt * 8 + g;
        __half* dst = g_w3f + (size_t)idx * 4;
#pragma unroll
        for (int q = 0; q < 4; q++) {
            int kq = ks * 16 + 2 * t + (q & 1) + (q >> 1) * 8;
            float v = (tap < 25) ? w3[(size_t)u * 800 + kq * 25 + tap] : 0.f;
            __half h = __float2half_rn(v);
            dst[q] = (hl == 0) ? h : __float2half_rn(v - __half2float(h));
        }
    }
}

// ---------------------------------------------------------------------------
// bilinear (half-pixel centers, clamp) — used by fused MSF input path.
// ---------------------------------------------------------------------------
__device__ __forceinline__ float bilin(const float* __restrict__ p, int N,
                                       float inv_s, int y, int x) {
    float sy = (y + 0.5f) * inv_s - 0.5f;
    float sx = (x + 0.5f) * inv_s - 0.5f;
    float fy0 = floorf(sy), fx0 = floorf(sx);
    float fy = sy - fy0, fx = sx - fx0;
    int y0 = (int)fy0, x0 = (int)fx0;
    int y0c = min(max(y0, 0), N - 1);
    int y1c = min(max(y0 + 1, 0), N - 1);
    int x0c = min(max(x0, 0), N - 1);
    int x1c = min(max(x0 + 1, 0), N - 1);
    float v00 = p[(size_t)y0c * N + x0c];
    float v01 = p[(size_t)y0c * N + x1c];
    float v10 = p[(size_t)y1c * N + x0c];
    float v11 = p[(size_t)y1c * N + x1c];
    return (1.f - fy) * ((1.f - fx) * v00 + fx * v01) +
           fy * ((1.f - fx) * v10 + fx * v11);
}

// ---------------------------------------------------------------------------
// conv1: 9x9, 1->64, ReLU via fp16 mma, split activations.
// Weight staging happens pre-wait when early_w=1 (weights are >=2 kernels old).
// msf_mode: input = x16 + up8(x2) + up4(x4) + up2(x8) computed inline.
// ---------------------------------------------------------------------------
__global__ __launch_bounds__(256) void conv1_mma_kernel(
    const float* __restrict__ in, const __half* __restrict__ wt,
    const float* __restrict__ bias, __half* __restrict__ out,
    int H, int W, int nu, int msf_mode,
    const float* __restrict__ mx2, const float* __restrict__ mx4,
    const float* __restrict__ mx8, int early_w)
{
    __shared__ __half s_h[24 * 24];
    __shared__ __half s_l[24 * 24];
    __shared__ __half s_w[6144];
    __shared__ float s_b[64];

    int z = blockIdx.z;
    int u = z % nu;
    int b = z / nu;
    int tid = threadIdx.x;
    int warp = tid >> 5;
    int lane = tid & 31;
    int x0 = blockIdx.x * 16, y0 = blockIdx.y * 16;
    const float* inb = in + (size_t)b * H * W;
    const __half* wu = wt + (size_t)u * 6144;

    if (early_w) {
        for (int i = tid; i < 768; i += 256)
            ((uint4*)s_w)[i] = ((const uint4*)wu)[i];
        if (tid < 64) s_b[tid] = bias[u * 64 + tid];
        gdc_wait();
    } else {
        gdc_wait();
        for (int i = tid; i < 768; i += 256)
            ((uint4*)s_w)[i] = ((const uint4*)wu)[i];
        if (tid < 64) s_b[tid] = bias[u * 64 + tid];
    }
    gdc_launch();

    for (int i = tid; i < 576; i += 256) {
        int iy = i / 24, ix = i - iy * 24;
        int gy = y0 + iy - 4, gx = x0 + ix - 4;
        float v = 0.f;
        if (gy >= 0 && gy < H && gx >= 0 && gx < W) {
            if (!msf_mode) {
                v = inb[(size_t)gy * W + gx];
            } else {
                v = inb[(size_t)gy * W + gx]
                  + bilin(mx2 + (size_t)b * 16384, 128, 0.125f, gy, gx)
                  + bilin(mx4 + (size_t)b * 65536, 256, 0.25f, gy, gx)
                  + bilin(mx8 + (size_t)b * 262144, 512, 0.5f, gy, gx);
            }
        }
        __half h = __float2half_rn(v);
        s_h[i] = h;
        s_l[i] = __float2half_rn(v - __half2float(h));
    }
    __syncthreads();

    int g = lane >> 2, t = lane & 3;
    int r0 = warp * 2;

    float c[2][8][4];
#pragma unroll
    for (int m = 0; m < 2; m++)
#pragma unroll
        for (int nt = 0; nt < 8; nt++)
#pragma unroll
            for (int q = 0; q < 4; q++) c[m][nt][q] = 0.f;

#pragma unroll
    for (int kc = 0; kc < 6; kc++) {
        uint2 breg[8];
#pragma unroll
        for (int nt = 0; nt < 8; nt++)
            breg[nt] = *(const uint2*)&s_w[((kc * 8 + nt) * 32 + lane) * 4];

        int o[4];
#pragma unroll
        for (int q = 0; q < 4; q++) {
            int tap = kc * 16 + 2 * t + (q & 1) + (q >> 1) * 8;
            tap = min(tap, 80);
            int dy = tap / 9, dx = tap - 9 * dy;
            o[q] = dy * 24 + dx;
        }

#pragma unroll
        for (int mrow = 0; mrow < 2; mrow++) {
            int base = (r0 + mrow) * 24;
            const __half* sh = s_h + base;
            const __half* sl = s_l + base;
            uint4 ah, al;
            ah.x = pkh(sh[o[0] + g],     sh[o[1] + g]);
            ah.y = pkh(sh[o[0] + g + 8], sh[o[1] + g + 8]);
            ah.z = pkh(sh[o[2] + g],     sh[o[3] + g]);
            ah.w = pkh(sh[o[2] + g + 8], sh[o[3] + g + 8]);
            al.x = pkh(sl[o[0] + g],     sl[o[1] + g]);
            al.y = pkh(sl[o[0] + g + 8], sl[o[1] + g + 8]);
            al.z = pkh(sl[o[2] + g],     sl[o[3] + g]);
            al.w = pkh(sl[o[2] + g + 8], sl[o[3] + g + 8]);
#pragma unroll
            for (int nt = 0; nt < 8; nt++) {
                mma_f16(c[mrow][nt], ah, breg[nt].x, breg[nt].y);
                mma_f16(c[mrow][nt], al, breg[nt].x, breg[nt].y);
            }
        }
    }

#pragma unroll
    for (int mrow = 0; mrow < 2; mrow++) {
        int y = y0 + r0 + mrow;
#pragma unroll
        for (int nt = 0; nt < 8; nt++) {
            int oc0 = nt * 8 + 2 * t;
            float bv0 = s_b[oc0], bv1 = s_b[oc0 + 1];
            __half2 v0 = __halves2half2(
                __float2half_rn(fmaxf(c[mrow][nt][0] + bv0, 0.f)),
                __float2half_rn(fmaxf(c[mrow][nt][1] + bv1, 0.f)));
            __half2 v1 = __halves2half2(
                __float2half_rn(fmaxf(c[mrow][nt][2] + bv0, 0.f)),
                __float2half_rn(fmaxf(c[mrow][nt][3] + bv1, 0.f)));
            *(__half2*)(out + (((size_t)z * H + y) * W + x0 + g) * 64 + oc0) = v0;
            *(__half2*)(out + (((size_t)z * H + y) * W + x0 + g + 8) * 64 + oc0) = v1;
        }
    }
}

// ---------------------------------------------------------------------------
// conv2: 5x5, 64->32, ReLU via fp16 mma, cp.async double-buffered, 16x16 tile.
// Chunk-0 weights issued pre-wait (PDL overlap). Output: (hi,lo) interleaved.
// ---------------------------------------------------------------------------
#define C2_SMEM 76800

__global__ __launch_bounds__(256) void conv2_mma_kernel(
    const __half* __restrict__ in,    // [z][H][W][64] fp16
    const __half* __restrict__ wt,    // [nu][4][25][2][32][8] frag-major
    const float* __restrict__ bias,   // [nu][32]
    __half* __restrict__ out,         // [z][H][W][64] (hi,lo interleaved)
    int H, int W, int nu)
{
    extern __shared__ __half s2[];
    __half* s_raw = s2;            // [2][400*16]
    __half* s_wt  = s2 + 12800;    // [2][12800]

    int z = blockIdx.z;
    int u = z % nu;
    int tid = threadIdx.x;
    int warp = tid >> 5;
    int lane = tid & 31;
    int x0 = blockIdx.x * 16, y0 = blockIdx.y * 16;
    const __half* inz = in + (size_t)z * H * W * 64;
    const __half* wu = wt + (size_t)u * 4 * 12800;

    int g = lane >> 2, t = lane & 3;
    int r0 = warp * 2;

    int bbase[4];
#pragma unroll
    for (int j = 0; j < 4; j++)
        bbase[j] = ((r0 + (j >> 1)) * 20 + (j & 1) * 8 + g) * 16 + 2 * t;

    float c[2][4][4];
#pragma unroll
    for (int m = 0; m < 2; m++)
#pragma unroll
        for (int j = 0; j < 4; j++)
#pragma unroll
            for (int q = 0; q < 4; q++) c[m][j][q] = 0.f;

    uint32_t raw_sm0 = smem_u32(s_raw);
    uint32_t wt_sm0 = smem_u32(s_wt);

    auto issue_weights = [&](int ch) {
        uint32_t ww = wt_sm0 + (ch & 1) * 25600;
        const uint4* wsrc = (const uint4*)(wu + (size_t)ch * 12800);
#pragma unroll
        for (int l = 0; l < 7; l++) {
            int i = tid + l * 256;
            if (i < 1600) cpa16(ww + i * 16, wsrc + i, true);
        }
    };
    auto issue_acts = [&](int ch) {
        uint32_t raw = raw_sm0 + (ch & 1) * 12800;
#pragma unroll
        for (int l = 0; l < 4; l++) {
            int i = tid + l * 256;
            if (i < 800) {
                int site = i >> 1, part = i & 1;
                int py = site / 20, px = site - py * 20;
                int gy = y0 + py - 2, gx = x0 + px - 2;
                bool ok = (gy >= 0 && gy < H && gx >= 0 && gx < W);
                const void* src = ok
                    ? (const void*)&inz[((size_t)gy * W + gx) * 64 + ch * 16 + part * 8]
                    : (const void*)inz;
                cpa16(raw + site * 32 + part * 16, src, ok);
            }
        }
    };

    issue_weights(0);      // weights are >=2 kernels old: safe pre-wait
    gdc_wait();
    gdc_launch();
    issue_acts(0);
    CP_COMMIT();

#pragma unroll
    for (int ch = 0; ch < 4; ch++) {
        if (ch > 0) __syncthreads();
        if (ch < 3) { issue_weights(ch + 1); issue_acts(ch + 1); CP_COMMIT(); }
        if (ch < 3) { CP_WAIT(1); } else { CP_WAIT(0); }
        __syncthreads();

        const __half* raw = s_raw + (ch & 1) * 6400;
        const __half* sw  = s_wt  + (ch & 1) * 12800;

#pragma unroll
        for (int dy = 0; dy < 5; dy++) {
#pragma unroll
            for (int dx = 0; dx < 5; dx++) {
                int tap = dy * 5 + dx;
                int toff = (dy * 20 + dx) * 16;
                uint4 a0 = *(const uint4*)&sw[(size_t)(tap * 2 + 0) * 256 + lane * 8];
                uint4 a1 = *(const uint4*)&sw[(size_t)(tap * 2 + 1) * 256 + lane * 8];
#pragma unroll
                for (int j = 0; j < 4; j++) {
                    unsigned b0 = *(const unsigned*)&raw[bbase[j] + toff];
                    unsigned b1 = *(const unsigned*)&raw[bbase[j] + toff + 8];
                    mma_f16(c[0][j], a0, b0, b1);
                    mma_f16(c[1][j], a1, b0, b1);
                }
            }
        }
    }

#pragma unroll
    for (int m = 0; m < 2; m++) {
        int oc0 = m * 16 + g;
        float bv0 = bias[u * 32 + oc0];
        float bv1 = bias[u * 32 + oc0 + 8];
#pragma unroll
        for (int j = 0; j < 4; j++) {
            int y = y0 + r0 + (j >> 1);
            int xb = x0 + (j & 1) * 8 + 2 * t;
            __half* base = out + (((size_t)z * H + y) * W + xb) * 64;
            st_hl(base + oc0 * 2,            fmaxf(c[m][j][0] + bv0, 0.f));
            st_hl(base + 64 + oc0 * 2,       fmaxf(c[m][j][1] + bv0, 0.f));
            st_hl(base + (oc0 + 8) * 2,      fmaxf(c[m][j][2] + bv1, 0.f));
            st_hl(base + 64 + (oc0 + 8) * 2, fmaxf(c[m][j][3] + bv1, 0.f));
        }
    }
}

// ---------------------------------------------------------------------------
// conv3: 5x5, 32->1 via site-GEMM D[site,tap] then fp32 tap-sum.
// 3 compensated passes: Ah*Wh + Al*Wh + Ah*Wl.  16x16 out tile, 256 thr.
// ---------------------------------------------------------------------------
#define C3_AL_OFF  36864
#define C3_WF_OFF  73728
#define C3_SMEM    77824

__global__ __launch_bounds__(256) void conv3_mma_kernel(
    const __half* __restrict__ in,   // t2 (hi,lo) [z][H][W][64]
    const __half* __restrict__ wf,   // [u][2][4][2][32][4]
    const float* __restrict__ b3, float* __restrict__ out,
    int H, int W, int nu, int interleave)
{
    extern __shared__ char cs[];
    __half* s_ah = (__half*)cs;               // [512*36]
    __half* s_al = (__half*)(cs + C3_AL_OFF); // [512*36]
    float*  s_d  = (float*)cs;                // alias: [512*34]
    __half* s_wf = (__half*)(cs + C3_WF_OFF); // 2048 halves

    int z = blockIdx.z;
    int u = z % nu;
    int b = z / nu;
    int tid = threadIdx.x;
    int warp = tid >> 5;
    int lane = tid & 31;
    int g = lane >> 2, t = lane & 3;
    int x0 = blockIdx.x * 16, y0 = blockIdx.y * 16;
    const __half* inz = in + (size_t)z * H * W * 64;

    // weights + bias staged pre-wait (written by prep, >=2 kernels back)
    ((uint4*)s_wf)[tid] = ((const uint4*)(wf + (size_t)u * 2048))[tid];
    float bacc = b3[u];
    gdc_wait();
    gdc_launch();

    for (int i = tid; i < 4096; i += 256) {
        int site = i >> 3, k = i & 7;
        uint4 v = make_uint4(0, 0, 0, 0);
        if (site < 400) {
            int sy = site / 20, sx = site - sy * 20;
            int gy = y0 + sy - 2, gx = x0 + sx - 2;
            if (gy >= 0 && gy < H && gx >= 0 && gx < W)
                v = *(const uint4*)(inz + ((size_t)gy * W + gx) * 64 + k * 8);
        }
        unsigned h01 = __byte_perm(v.x, v.y, 0x5410);
        unsigned l01 = __byte_perm(v.x, v.y, 0x7632);
        unsigned h23 = __byte_perm(v.z, v.w, 0x5410);
        unsigned l23 = __byte_perm(v.z, v.w, 0x7632);
        int off = site * 36 + k * 4;
        *(uint2*)&s_ah[off] = make_uint2(h01, h23);
        *(uint2*)&s_al[off] = make_uint2(l01, l23);
    }
    __syncthreads();

    uint2 bh[4][2], bl[4][2];
#pragma unroll
    for (int nt = 0; nt < 4; nt++)
#pragma unroll
        for (int ks = 0; ks < 2; ks++) {
            bh[nt][ks] = ((const uint2*)s_wf)[(nt * 2 + ks) * 32 + lane];
            bl[nt][ks] = ((const uint2*)s_wf)[((4 + nt) * 2 + ks) * 32 + lane];
        }

    float c[4][4][4];
#pragma unroll
    for (int mt = 0; mt < 4; mt++)
#pragma unroll
        for (int nt = 0; nt < 4; nt++)
#pragma unroll
            for (int q = 0; q < 4; q++) c[mt][nt][q] = 0.f;

#pragma unroll
    for (int mt = 0; mt < 4; mt++) {
        int m0 = (warp * 4 + mt) * 16;
#pragma unroll
        for (int ks = 0; ks < 2; ks++) {
            int ko = ks * 16 + 2 * t;
            uint4 ah, al;
            ah.x = *(const unsigned*)&s_ah[(m0 + g) * 36 + ko];
            ah.y = *(const unsigned*)&s_ah[(m0 + g + 8) * 36 + ko];
            ah.z = *(const unsigned*)&s_ah[(m0 + g) * 36 + ko + 8];
            ah.w = *(const unsigned*)&s_ah[(m0 + g + 8) * 36 + ko + 8];
            al.x = *(const unsigned*)&s_al[(m0 + g) * 36 + ko];
            al.y = *(const unsigned*)&s_al[(m0 + g + 8) * 36 + ko];
            al.z = *(const unsigned*)&s_al[(m0 + g) * 36 + ko + 8];
            al.w = *(const unsigned*)&s_al[(m0 + g + 8) * 36 + ko + 8];
#pragma unroll
            for (int nt = 0; nt < 4; nt++) {
                mma_f16(c[mt][nt], ah, bh[nt][ks].x, bh[nt][ks].y);
                mma_f16(c[mt][nt], al, bh[nt][ks].x, bh[nt][ks].y);
                mma_f16(c[mt][nt], ah, bl[nt][ks].x, bl[nt][ks].y);
            }
        }
    }
    __syncthreads();

#pragma unroll
    for (int mt = 0; mt < 4; mt++) {
        int m0 = (warp * 4 + mt) * 16;
#pragma unroll
        for (int nt = 0; nt < 4; nt++) {
            int col = nt * 8 + 2 * t;
            *(float2*)&s_d[(m0 + g) * 34 + col] =
                make_float2(c[mt][nt][0], c[mt][nt][1]);
            *(float2*)&s_d[(m0 + g + 8) * 34 + col] =
                make_float2(c[mt][nt][2], c[mt][nt][3]);
        }
    }
    __syncthreads();

    int ty = tid >> 4, tx = tid & 15;
    float acc = bacc;
#pragma unroll
    for (int dy = 0; dy < 5; dy++)
#pragma unroll
        for (int dx = 0; dx < 5; dx++)
            acc += s_d[((ty + dy) * 20 + tx + dx) * 34 + dy * 5 + dx];

    int y = y0 + ty, x = x0 + tx;
    if (interleave) {
        int uy = u >> 1, ux = u & 1;
        out[(size_t)b * 4 * H * W + (size_t)(2 * y + uy) * (2 * W) + 2 * x + ux] = acc;
    } else {
        out[(size_t)b * H * W + (size_t)y * W + x] = acc;
    }
}

// ---------------------------------------------------------------------------
// Host orchestration — PDL-chained launches via cudaLaunchKernelEx.
// ---------------------------------------------------------------------------
extern "C" void kernel_launch(void* const* d_in, const int* in_sizes, int n_in,
                              void* d_out, int out_size) {
    const float* image = (const float*)d_in[0];
    const float* w1 = (const float*)d_in[1];
    const float* b1 = (const float*)d_in[2];
    const float* w2 = (const float*)d_in[3];
    const float* b2 = (const float*)d_in[4];
    const float* w3 = (const float*)d_in[5];
    const float* b3 = (const float*)d_in[6];
    float* out = (float*)d_out;

    __half *t1h, *t2hl, *w1h, *w2h, *w3f;
    cudaGetSymbolAddress((void**)&t1h, g_t1h);
    cudaGetSymbolAddress((void**)&t2hl, g_t2hl);
    cudaGetSymbolAddress((void**)&w1h, g_w1h);
    cudaGetSymbolAddress((void**)&w2h, g_w2h);
    cudaGetSymbolAddress((void**)&w3f, g_w3f);

    static bool attr_done = false;
    if (!attr_done) {
        cudaFuncSetAttribute(conv2_mma_kernel,
                             cudaFuncAttributeMaxDynamicSharedMemorySize, C2_SMEM);
        cudaFuncSetAttribute(conv3_mma_kernel,
                             cudaFuncAttributeMaxDynamicSharedMemorySize, C3_SMEM);
        attr_done = true;
    }

    prep_weights_kernel<<<850, 256>>>(w1, w2, w3);

    float* ox2 = out + 0;
    float* ox4 = out + 32768;
    float* ox8 = out + 163840;
    float* ox16 = out + 688128;
    float* omsf = out + 2785280;

    cudaLaunchAttribute pss[1];
    pss[0].id = cudaLaunchAttributeProgrammaticStreamSerialization;
    pss[0].val.programmaticStreamSerializationAllowed = 1;

    auto mkcfg = [&](dim3 grid, size_t smem) {
        cudaLaunchConfig_t c = {};
        c.gridDim = grid;
        c.blockDim = dim3(256, 1, 1);
        c.dynamicSmemBytes = smem;
        c.stream = 0;
        c.attrs = pss;
        c.numAttrs = 1;
        return c;
    };

    auto run_stage = [&](const float* inp, int H, int W, int ubase,
                         float* outp, int nu, int il, int msf_mode, int early_w) {
        dim3 g1(W / 16, H / 16, 2 * nu);
        cudaLaunchConfig_t c1 = mkcfg(g1, 0);
        cudaLaunchKernelEx(&c1, conv1_mma_kernel,
                           inp, (const __half*)(w1h + (size_t)ubase * 6144),
                           (const float*)(b1 + (size_t)ubase * 64),
                           t1h, H, W, nu, msf_mode,
                           (const float*)ox2, (const float*)ox4,
                           (const float*)ox8, early_w);
        cudaLaunchConfig_t c2 = mkcfg(g1, C2_SMEM);
        cudaLaunchKernelEx(&c2, conv2_mma_kernel,
                           (const __half*)t1h,
                           (const __half*)(w2h + (size_t)ubase * 4 * 12800),
                           (const float*)(b2 + (size_t)ubase * 32),
                           t2hl, H, W, nu);
        cudaLaunchConfig_t c3 = mkcfg(g1, C3_SMEM);
        cudaLaunchKernelEx(&c3, conv3_mma_kernel,
                           (const __half*)t2hl,
                           (const __half*)(w3f + (size_t)ubase * 2048),
                           (const float*)(b3 + ubase),
                           outp, H, W, nu, il);
    };

    run_stage(image, 64, 64, 0, ox2, 4, 1, 0, 0);     // conv1 waits before weights
    run_stage(ox2, 128, 128, 4, ox4, 4, 1, 0, 1);
    run_stage(ox4, 256, 256, 8, ox8, 4, 1, 0, 1);
    run_stage(ox8, 512, 512, 12, ox16, 4, 1, 0, 1);
    // MSF stage: conv1 computes x16 + up8(x2)+up4(x4)+up2(x8) inline from ox16.
    run_stage(ox16, 1024, 1024, 16, omsf, 1, 0, 1, 1);
}

// round 13
// speedup vs baseline: 1.0045x; 1.0045x over previous
#include <cuda_runtime.h>
#include <cuda_fp16.h>
#include <cstdint>

// ---------------------------------------------------------------------------
// DSDMSR multi-scale SRCNN cascade (sm_100 / compute_100 legacy mma path).
// conv1 (9x9,1->64): fp16 mma, split hi/lo activations; MSF input fused.
// conv2 (5x5,64->32): fp16 mma m16n8k16, cp.async double-buffered, 16x16 tile.
// conv3 (5x5,32->1): site-GEMM, 3-pass compensated + fp32 tap-sum.
// All conv kernels chained with PDL (programmatic dependent launch):
// weight staging overlaps the predecessor kernel's tail.
// ---------------------------------------------------------------------------

__device__ __half g_t1h[134217728];          // conv1 out, [z][H][W][64] fp16
__device__ __half g_t2hl[134217728];         // conv2 out, [z][H][W][32*(hi,lo)]
__device__ __half g_w1h[17 * 6 * 8 * 32 * 4];      // conv1 w frag-major
__device__ __half g_w2h[17 * 4 * 25 * 2 * 32 * 8]; // conv2 w frag-major
__device__ __half g_w3f[17 * 2048];                // conv3 w frag-major (hi,lo)

__device__ __forceinline__ unsigned pkh(__half a, __half b) {
    __half2 p = __halves2half2(a, b);
    return *(unsigned*)&p;
}
__device__ __forceinline__ void mma_f16(float c[4], const uint4& a,
                                        unsigned b0, unsigned b1) {
    asm volatile(
        "mma.sync.aligned.m16n8k16.row.col.f32.f16.f16.f32 "
        "{%0,%1,%2,%3}, {%4,%5,%6,%7}, {%8,%9}, {%0,%1,%2,%3};"
        : "+f"(c[0]), "+f"(c[1]), "+f"(c[2]), "+f"(c[3])
        : "r"(a.x), "r"(a.y), "r"(a.z), "r"(a.w), "r"(b0), "r"(b1));
}
__device__ __forceinline__ void st_hl(__half* p, float v) {
    __half h = __float2half_rn(v);
    __half l = __float2half_rn(v - __half2float(h));
    *(__half2*)p = __halves2half2(h, l);
}
__device__ __forceinline__ uint32_t smem_u32(const void* p) {
    uint32_t a;
    asm("{ .reg .u64 t; cvta.to.shared.u64 t, %1; cvt.u32.u64 %0, t; }"
        : "=r"(a) : "l"(p));
    return a;
}
__device__ __forceinline__ void cpa16(uint32_t s, const void* g, bool pred) {
    int sz = pred ? 16 : 0;
    asm volatile("cp.async.cg.shared.global [%0], [%1], 16, %2;"
                 :: "r"(s), "l"(g), "r"(sz) : "memory");
}
#define CP_COMMIT() asm volatile("cp.async.commit_group;" ::: "memory")
#define CP_WAIT(n)  asm volatile("cp.async.wait_group %0;" :: "n"(n) : "memory")
__device__ __forceinline__ void gdc_wait() {
    asm volatile("griddepcontrol.wait;" ::: "memory");
}
__device__ __forceinline__ void gdc_launch() {
    asm volatile("griddepcontrol.launch_dependents;");
}

// ---------------------------------------------------------------------------
// Weight prep: w1 frag-major, w2 frag-major, w3 frag-major hi/lo.
// ---------------------------------------------------------------------------
__global__ void prep_weights_kernel(const float* __restrict__ w1,
                                    const float* __restrict__ w2,
                                    const float* __restrict__ w3) {
    int idx = blockIdx.x * 256 + threadIdx.x;
    if (idx < 17 * 6 * 8 * 32) {
        int lane = idx & 31;
        int r = idx >> 5;
        int nt = r & 7; r >>= 3;
        int kc = r % 6;
        int u = r / 6;
        int g = lane >> 2, t = lane & 3;
        int oc = nt * 8 + g;
        int kt[4] = {kc * 16 + 2 * t, kc * 16 + 2 * t + 1,
                     kc * 16 + 2 * t + 8, kc * 16 + 2 * t + 9};
        __half* dst = g_w1h + (size_t)idx * 4;
#pragma unroll
        for (int q = 0; q < 4; q++)
            dst[q] = (kt[q] < 81)
                ? __float2half_rn(w1[((size_t)u * 64 + oc) * 81 + kt[q]])
                : __half(0.f);
    }
    if (idx < 17 * 4 * 25 * 2 * 32) {
        int l = idx & 31;
        int m = (idx >> 5) & 1;
        int rest = idx >> 6;
        int tap = rest % 25;
        int rest2 = rest / 25;
        int ch = rest2 & 3;
        int u = rest2 >> 2;
        int g = l >> 2, t = l & 3;
        int oc0 = m * 16 + g;
        int ic0 = ch * 16;
        __half* dst = g_w2h + (size_t)idx * 8;
#pragma unroll
        for (int q = 0; q < 8; q++) {
            int oc = oc0 + ((q >> 1) & 1) * 8;
            int ic = ic0 + 2 * t + (q & 1) + (q >> 2) * 8;
            dst[q] = __float2half_rn(w2[((size_t)(u * 32 + oc) * 64 + ic) * 25 + tap]);
        }
    }
    if (idx < 17 * 2 * 4 * 2 * 32) {
        int lane = idx & 31;
        int r = idx >> 5;
        int ks = r & 1; r >>= 1;
        int nt = r & 3; r >>= 2;
        int hl = r & 1; r >>= 1;
        int u = r;
        int g = lane >> 2, t = lane & 3;
        int tap = nt * 8 + g;
        __half* dst = g_w3f + (size_t)idx * 4;
#pragma unroll
        for (int q = 0; q < 4; q++) {
            int kq = ks * 16 + 2 * t + (q & 1) + (q >> 1) * 8;
            float v = (tap < 25) ? w3[(size_t)u * 800 + kq * 25 + tap] : 0.f;
            __half h = __float2half_rn(v);
            dst[q] = (hl == 0) ? h : __float2half_rn(v - __half2float(h));
        }
    }
}

// ---------------------------------------------------------------------------
// bilinear (half-pixel centers, clamp) — used by fused MSF input path.
// ---------------------------------------------------------------------------
__device__ __forceinline__ float bilin(const float* __restrict__ p, int N,
                                       float inv_s, int y, int x) {
    float sy = (y + 0.5f) * inv_s - 0.5f;
    float sx = (x + 0.5f) * inv_s - 0.5f;
    float fy0 = floorf(sy), fx0 = floorf(sx);
    float fy = sy - fy0, fx = sx - fx0;
    int y0 = (int)fy0, x0 = (int)fx0;
    int y0c = min(max(y0, 0), N - 1);
    int y1c = min(max(y0 + 1, 0), N - 1);
    int x0c = min(max(x0, 0), N - 1);
    int x1c = min(max(x0 + 1, 0), N - 1);
    float v00 = p[(size_t)y0c * N + x0c];
    float v01 = p[(size_t)y0c * N + x1c];
    float v10 = p[(size_t)y1c * N + x0c];
    float v11 = p[(size_t)y1c * N + x1c];
    return (1.f - fy) * ((1.f - fx) * v00 + fx * v01) +
           fy * ((1.f - fx) * v10 + fx * v11);
}

// ---------------------------------------------------------------------------
// conv1: 9x9, 1->64, ReLU via fp16 mma, split activations.
// Weight staging happens pre-wait when early_w=1 (weights are >=2 kernels old).
// msf_mode: input = x16 + up8(x2) + up4(x4) + up2(x8) computed inline.
// ---------------------------------------------------------------------------
__global__ __launch_bounds__(256) void conv1_mma_kernel(
    const float* __restrict__ in, const __half* __restrict__ wt,
    const float* __restrict__ bias, __half* __restrict__ out,
    int H, int W, int nu, int msf_mode,
    const float* __restrict__ mx2, const float* __restrict__ mx4,
    const float* __restrict__ mx8, int early_w)
{
    __shared__ __half s_h[24 * 24];
    __shared__ __half s_l[24 * 24];
    __shared__ __half s_w[6144];
    __shared__ float s_b[64];

    int z = blockIdx.z;
    int u = z % nu;
    int b = z / nu;
    int tid = threadIdx.x;
    int warp = tid >> 5;
    int lane = tid & 31;
    int x0 = blockIdx.x * 16, y0 = blockIdx.y * 16;
    const float* inb = in + (size_t)b * H * W;
    const __half* wu = wt + (size_t)u * 6144;

    if (early_w) {
        for (int i = tid; i < 768; i += 256)
            ((uint4*)s_w)[i] = ((const uint4*)wu)[i];
        if (tid < 64) s_b[tid] = bias[u * 64 + tid];
        gdc_wait();
    } else {
        gdc_wait();
        for (int i = tid; i < 768; i += 256)
            ((uint4*)s_w)[i] = ((const uint4*)wu)[i];
        if (tid < 64) s_b[tid] = bias[u * 64 + tid];
    }
    gdc_launch();

    for (int i = tid; i < 576; i += 256) {
        int iy = i / 24, ix = i - iy * 24;
        int gy = y0 + iy - 4, gx = x0 + ix - 4;
        float v = 0.f;
        if (gy >= 0 && gy < H && gx >= 0 && gx < W) {
            if (!msf_mode) {
                v = inb[(size_t)gy * W + gx];
            } else {
                v = inb[(size_t)gy * W + gx]
                  + bilin(mx2 + (size_t)b * 16384, 128, 0.125f, gy, gx)
                  + bilin(mx4 + (size_t)b * 65536, 256, 0.25f, gy, gx)
                  + bilin(mx8 + (size_t)b * 262144, 512, 0.5f, gy, gx);
            }
        }
        __half h = __float2half_rn(v);
        s_h[i] = h;
        s_l[i] = __float2half_rn(v - __half2float(h));
    }
    __syncthreads();

    int g = lane >> 2, t = lane & 3;
    int r0 = warp * 2;

    float c[2][8][4];
#pragma unroll
    for (int m = 0; m < 2; m++)
#pragma unroll
        for (int nt = 0; nt < 8; nt++)
#pragma unroll
            for (int q = 0; q < 4; q++) c[m][nt][q] = 0.f;

#pragma unroll
    for (int kc = 0; kc < 6; kc++) {
        uint2 breg[8];
#pragma unroll
        for (int nt = 0; nt < 8; nt++)
            breg[nt] = *(const uint2*)&s_w[((kc * 8 + nt) * 32 + lane) * 4];

        int o[4];
#pragma unroll
        for (int q = 0; q < 4; q++) {
            int tap = kc * 16 + 2 * t + (q & 1) + (q >> 1) * 8;
            tap = min(tap, 80);
            int dy = tap / 9, dx = tap - 9 * dy;
            o[q] = dy * 24 + dx;
        }

#pragma unroll
        for (int mrow = 0; mrow < 2; mrow++) {
            int base = (r0 + mrow) * 24;
            const __half* sh = s_h + base;
            const __half* sl = s_l + base;
            uint4 ah, al;
            ah.x = pkh(sh[o[0] + g],     sh[o[1] + g]);
            ah.y = pkh(sh[o[0] + g + 8], sh[o[1] + g + 8]);
            ah.z = pkh(sh[o[2] + g],     sh[o[3] + g]);
            ah.w = pkh(sh[o[2] + g + 8], sh[o[3] + g + 8]);
            al.x = pkh(sl[o[0] + g],     sl[o[1] + g]);
            al.y = pkh(sl[o[0] + g + 8], sl[o[1] + g + 8]);
            al.z = pkh(sl[o[2] + g],     sl[o[3] + g]);
            al.w = pkh(sl[o[2] + g + 8], sl[o[3] + g + 8]);
#pragma unroll
            for (int nt = 0; nt < 8; nt++) {
                mma_f16(c[mrow][nt], ah, breg[nt].x, breg[nt].y);
                mma_f16(c[mrow][nt], al, breg[nt].x, breg[nt].y);
            }
        }
    }

#pragma unroll
    for (int mrow = 0; mrow < 2; mrow++) {
        int y = y0 + r0 + mrow;
#pragma unroll
        for (int nt = 0; nt < 8; nt++) {
            int oc0 = nt * 8 + 2 * t;
            float bv0 = s_b[oc0], bv1 = s_b[oc0 + 1];
            __half2 v0 = __halves2half2(
                __float2half_rn(fmaxf(c[mrow][nt][0] + bv0, 0.f)),
                __float2half_rn(fmaxf(c[mrow][nt][1] + bv1, 0.f)));
            __half2 v1 = __halves2half2(
                __float2half_rn(fmaxf(c[mrow][nt][2] + bv0, 0.f)),
                __float2half_rn(fmaxf(c[mrow][nt][3] + bv1, 0.f)));
            *(__half2*)(out + (((size_t)z * H + y) * W + x0 + g) * 64 + oc0) = v0;
            *(__half2*)(out + (((size_t)z * H + y) * W + x0 + g + 8) * 64 + oc0) = v1;
        }
    }
}

// ---------------------------------------------------------------------------
// conv2: 5x5, 64->32, ReLU via fp16 mma, cp.async double-buffered, 16x16 tile.
// Chunk-0 weights issued pre-wait (PDL overlap). Output: (hi,lo) interleaved.
// ---------------------------------------------------------------------------
#define C2_SMEM 76800

__global__ __launch_bounds__(256) void conv2_mma_kernel(
    const __half* __restrict__ in,    // [z][H][W][64] fp16
    const __half* __restrict__ wt,    // [nu][4][25][2][32][8] frag-major
    const float* __restrict__ bias,   // [nu][32]
    __half* __restrict__ out,         // [z][H][W][64] (hi,lo interleaved)
    int H, int W, int nu)
{
    extern __shared__ __half s2[];
    __half* s_raw = s2;            // [2][400*16]
    __half* s_wt  = s2 + 12800;    // [2][12800]

    int z = blockIdx.z;
    int u = z % nu;
    int tid = threadIdx.x;
    int warp = tid >> 5;
    int lane = tid & 31;
    int x0 = blockIdx.x * 16, y0 = blockIdx.y * 16;
    const __half* inz = in + (size_t)z * H * W * 64;
    const __half* wu = wt + (size_t)u * 4 * 12800;

    int g = lane >> 2, t = lane & 3;
    int r0 = warp * 2;

    int bbase[4];
#pragma unroll
    for (int j = 0; j < 4; j++)
        bbase[j] = ((r0 + (j >> 1)) * 20 + (j & 1) * 8 + g) * 16 + 2 * t;

    float c[2][4][4];
#pragma unroll
    for (int m = 0; m < 2; m++)
#pragma unroll
        for (int j = 0; j < 4; j++)
#pragma unroll
            for (int q = 0; q < 4; q++) c[m][j][q] = 0.f;

    uint32_t raw_sm0 = smem_u32(s_raw);
    uint32_t wt_sm0 = smem_u32(s_wt);

    auto issue_weights = [&](int ch) {
        uint32_t ww = wt_sm0 + (ch & 1) * 25600;
        const uint4* wsrc = (const uint4*)(wu + (size_t)ch * 12800);
#pragma unroll
        for (int l = 0; l < 7; l++) {
            int i = tid + l * 256;
            if (i < 1600) cpa16(ww + i * 16, wsrc + i, true);
        }
    };
    auto issue_acts = [&](int ch) {
        uint32_t raw = raw_sm0 + (ch & 1) * 12800;
#pragma unroll
        for (int l = 0; l < 4; l++) {
            int i = tid + l * 256;
            if (i < 800) {
                int site = i >> 1, part = i & 1;
                int py = site / 20, px = site - py * 20;
                int gy = y0 + py - 2, gx = x0 + px - 2;
                bool ok = (gy >= 0 && gy < H && gx >= 0 && gx < W);
                const void* src = ok
                    ? (const void*)&inz[((size_t)gy * W + gx) * 64 + ch * 16 + part * 8]
                    : (const void*)inz;
                cpa16(raw + site * 32 + part * 16, src, ok);
            }
        }
    };

    issue_weights(0);      // weights are >=2 kernels old: safe pre-wait
    gdc_wait();
    gdc_launch();
    issue_acts(0);
    CP_COMMIT();

#pragma unroll
    for (int ch = 0; ch < 4; ch++) {
        if (ch > 0) __syncthreads();
        if (ch < 3) { issue_weights(ch + 1); issue_acts(ch + 1); CP_COMMIT(); }
        if (ch < 3) { CP_WAIT(1); } else { CP_WAIT(0); }
        __syncthreads();

        const __half* raw = s_raw + (ch & 1) * 6400;
        const __half* sw  = s_wt  + (ch & 1) * 12800;

#pragma unroll
        for (int dy = 0; dy < 5; dy++) {
#pragma unroll
            for (int dx = 0; dx < 5; dx++) {
                int tap = dy * 5 + dx;
                int toff = (dy * 20 + dx) * 16;
                uint4 a0 = *(const uint4*)&sw[(size_t)(tap * 2 + 0) * 256 + lane * 8];
                uint4 a1 = *(const uint4*)&sw[(size_t)(tap * 2 + 1) * 256 + lane * 8];
#pragma unroll
                for (int j = 0; j < 4; j++) {
                    unsigned b0 = *(const unsigned*)&raw[bbase[j] + toff];
                    unsigned b1 = *(const unsigned*)&raw[bbase[j] + toff + 8];
                    mma_f16(c[0][j], a0, b0, b1);
                    mma_f16(c[1][j], a1, b0, b1);
                }
            }
        }
    }

#pragma unroll
    for (int m = 0; m < 2; m++) {
        int oc0 = m * 16 + g;
        float bv0 = bias[u * 32 + oc0];
        float bv1 = bias[u * 32 + oc0 + 8];
#pragma unroll
        for (int j = 0; j < 4; j++) {
            int y = y0 + r0 + (j >> 1);
            int xb = x0 + (j & 1) * 8 + 2 * t;
            __half* base = out + (((size_t)z * H + y) * W + xb) * 64;
            st_hl(base + oc0 * 2,            fmaxf(c[m][j][0] + bv0, 0.f));
            st_hl(base + 64 + oc0 * 2,       fmaxf(c[m][j][1] + bv0, 0.f));
            st_hl(base + (oc0 + 8) * 2,      fmaxf(c[m][j][2] + bv1, 0.f));
            st_hl(base + 64 + (oc0 + 8) * 2, fmaxf(c[m][j][3] + bv1, 0.f));
        }
    }
}

// ---------------------------------------------------------------------------
// conv3: 5x5, 32->1 via site-GEMM D[site,tap] then fp32 tap-sum.
// 3 compensated passes: Ah*Wh + Al*Wh + Ah*Wl.  16x16 out tile, 256 thr.
// ---------------------------------------------------------------------------
#define C3_AL_OFF  36864
#define C3_WF_OFF  73728
#define C3_SMEM    77824

__global__ __launch_bounds__(256) void conv3_mma_kernel(
    const __half* __restrict__ in,   // t2 (hi,lo) [z][H][W][64]
    const __half* __restrict__ wf,   // [u][2][4][2][32][4]
    const float* __restrict__ b3, float* __restrict__ out,
    int H, int W, int nu, int interleave)
{
    extern __shared__ char cs[];
    __half* s_ah = (__half*)cs;               // [512*36]
    __half* s_al = (__half*)(cs + C3_AL_OFF); // [512*36]
    float*  s_d  = (float*)cs;                // alias: [512*34]
    __half* s_wf = (__half*)(cs + C3_WF_OFF); // 2048 halves

    int z = blockIdx.z;
    int u = z % nu;
    int b = z / nu;
    int tid = threadIdx.x;
    int warp = tid >> 5;
    int lane = tid & 31;
    int g = lane >> 2, t = lane & 3;
    int x0 = blockIdx.x * 16, y0 = blockIdx.y * 16;
    const __half* inz = in + (size_t)z * H * W * 64;

    // weights + bias staged pre-wait (written by prep, >=2 kernels back)
    ((uint4*)s_wf)[tid] = ((const uint4*)(wf + (size_t)u * 2048))[tid];
    float bacc = b3[u];
    gdc_wait();
    gdc_launch();

    for (int i = tid; i < 4096; i += 256) {
        int site = i >> 3, k = i & 7;
        uint4 v = make_uint4(0, 0, 0, 0);
        if (site < 400) {
            int sy = site / 20, sx = site - sy * 20;
            int gy = y0 + sy - 2, gx = x0 + sx - 2;
            if (gy >= 0 && gy < H && gx >= 0 && gx < W)
                v = *(const uint4*)(inz + ((size_t)gy * W + gx) * 64 + k * 8);
        }
        unsigned h01 = __byte_perm(v.x, v.y, 0x5410);
        unsigned l01 = __byte_perm(v.x, v.y, 0x7632);
        unsigned h23 = __byte_perm(v.z, v.w, 0x5410);
        unsigned l23 = __byte_perm(v.z, v.w, 0x7632);
        int off = site * 36 + k * 4;
        *(uint2*)&s_ah[off] = make_uint2(h01, h23);
        *(uint2*)&s_al[off] = make_uint2(l01, l23);
    }
    __syncthreads();

    uint2 bh[4][2], bl[4][2];
#pragma unroll
    for (int nt = 0; nt < 4; nt++)
#pragma unroll
        for (int ks = 0; ks < 2; ks++) {
            bh[nt][ks] = ((const uint2*)s_wf)[(nt * 2 + ks) * 32 + lane];
            bl[nt][ks] = ((const uint2*)s_wf)[((4 + nt) * 2 + ks) * 32 + lane];
        }

    float c[4][4][4];
#pragma unroll
    for (int mt = 0; mt < 4; mt++)
#pragma unroll
        for (int nt = 0; nt < 4; nt++)
#pragma unroll
            for (int q = 0; q < 4; q++) c[mt][nt][q] = 0.f;

#pragma unroll
    for (int mt = 0; mt < 4; mt++) {
        int m0 = (warp * 4 + mt) * 16;
#pragma unroll
        for (int ks = 0; ks < 2; ks++) {
            int ko = ks * 16 + 2 * t;
            uint4 ah, al;
            ah.x = *(const unsigned*)&s_ah[(m0 + g) * 36 + ko];
            ah.y = *(const unsigned*)&s_ah[(m0 + g + 8) * 36 + ko];
            ah.z = *(const unsigned*)&s_ah[(m0 + g) * 36 + ko + 8];
            ah.w = *(const unsigned*)&s_ah[(m0 + g + 8) * 36 + ko + 8];
            al.x = *(const unsigned*)&s_al[(m0 + g) * 36 + ko];
            al.y = *(const unsigned*)&s_al[(m0 + g + 8) * 36 + ko];
            al.z = *(const unsigned*)&s_al[(m0 + g) * 36 + ko + 8];
            al.w = *(const unsigned*)&s_al[(m0 + g + 8) * 36 + ko + 8];
#pragma unroll
            for (int nt = 0; nt < 4; nt++) {
                mma_f16(c[mt][nt], ah, bh[nt][ks].x, bh[nt][ks].y);
                mma_f16(c[mt][nt], al, bh[nt][ks].x, bh[nt][ks].y);
                mma_f16(c[mt][nt], ah, bl[nt][ks].x, bl[nt][ks].y);
            }
        }
    }
    __syncthreads();

#pragma unroll
    for (int mt = 0; mt < 4; mt++) {
        int m0 = (warp * 4 + mt) * 16;
#pragma unroll
        for (int nt = 0; nt < 4; nt++) {
            int col = nt * 8 + 2 * t;
            *(float2*)&s_d[(m0 + g) * 34 + col] =
                make_float2(c[mt][nt][0], c[mt][nt][1]);
            *(float2*)&s_d[(m0 + g + 8) * 34 + col] =
                make_float2(c[mt][nt][2], c[mt][nt][3]);
        }
    }
    __syncthreads();

    int ty = tid >> 4, tx = tid & 15;
    float acc = bacc;
#pragma unroll
    for (int dy = 0; dy < 5; dy++)
#pragma unroll
        for (int dx = 0; dx < 5; dx++)
            acc += s_d[((ty + dy) * 20 + tx + dx) * 34 + dy * 5 + dx];

    int y = y0 + ty, x = x0 + tx;
    if (interleave) {
        int uy = u >> 1, ux = u & 1;
        out[(size_t)b * 4 * H * W + (size_t)(2 * y + uy) * (2 * W) + 2 * x + ux] = acc;
    } else {
        out[(size_t)b * H * W + (size_t)y * W + x] = acc;
    }
}

// ---------------------------------------------------------------------------
// Host orchestration — PDL-chained launches via cudaLaunchKernelEx.
// ---------------------------------------------------------------------------
extern "C" void kernel_launch(void* const* d_in, const int* in_sizes, int n_in,
                              void* d_out, int out_size) {
    const float* image = (const float*)d_in[0];
    const float* w1 = (const float*)d_in[1];
    const float* b1 = (const float*)d_in[2];
    const float* w2 = (const float*)d_in[3];
    const float* b2 = (const float*)d_in[4];
    const float* w3 = (const float*)d_in[5];
    const float* b3 = (const float*)d_in[6];
    float* out = (float*)d_out;

    __half *t1h, *t2hl, *w1h, *w2h, *w3f;
    cudaGetSymbolAddress((void**)&t1h, g_t1h);
    cudaGetSymbolAddress((void**)&t2hl, g_t2hl);
    cudaGetSymbolAddress((void**)&w1h, g_w1h);
    cudaGetSymbolAddress((void**)&w2h, g_w2h);
    cudaGetSymbolAddress((void**)&w3f, g_w3f);

    static bool attr_done = false;
    if (!attr_done) {
        cudaFuncSetAttribute(conv2_mma_kernel,
                             cudaFuncAttributeMaxDynamicSharedMemorySize, C2_SMEM);
        cudaFuncSetAttribute(conv3_mma_kernel,
                             cudaFuncAttributeMaxDynamicSharedMemorySize, C3_SMEM);
        attr_done = true;
    }

    prep_weights_kernel<<<850, 256>>>(w1, w2, w3);

    float* ox2 = out + 0;
    float* ox4 = out + 32768;
    float* ox8 = out + 163840;
    float* ox16 = out + 688128;
    float* omsf = out + 2785280;

    cudaLaunchAttribute pss[1];
    pss[0].id = cudaLaunchAttributeProgrammaticStreamSerialization;
    pss[0].val.programmaticStreamSerializationAllowed = 1;

    auto mkcfg = [&](dim3 grid, size_t smem) {
        cudaLaunchConfig_t c = {};
        c.gridDim = grid;
        c.blockDim = dim3(256, 1, 1);
        c.dynamicSmemBytes = smem;
        c.stream = 0;
        c.attrs = pss;
        c.numAttrs = 1;
        return c;
    };

    auto run_stage = [&](const float* inp, int H, int W, int ubase,
                         float* outp, int nu, int il, int msf_mode, int early_w) {
        dim3 g1(W / 16, H / 16, 2 * nu);
        cudaLaunchConfig_t c1 = mkcfg(g1, 0);
        cudaLaunchKernelEx(&c1, conv1_mma_kernel,
                           inp, (const __half*)(w1h + (size_t)ubase * 6144),
                           (const float*)(b1 + (size_t)ubase * 64),
                           t1h, H, W, nu, msf_mode,
                           (const float*)ox2, (const float*)ox4,
                           (const float*)ox8, early_w);
        cudaLaunchConfig_t c2 = mkcfg(g1, C2_SMEM);
        cudaLaunchKernelEx(&c2, conv2_mma_kernel,
                           (const __half*)t1h,
                           (const __half*)(w2h + (size_t)ubase * 4 * 12800),
                           (const float*)(b2 + (size_t)ubase * 32),
                           t2hl, H, W, nu);
        cudaLaunchConfig_t c3 = mkcfg(g1, C3_SMEM);
        cudaLaunchKernelEx(&c3, conv3_mma_kernel,
                           (const __half*)t2hl,
                           (const __half*)(w3f + (size_t)ubase * 2048),
                           (const float*)(b3 + ubase),
                           outp, H, W, nu, il);
    };

    run_stage(image, 64, 64, 0, ox2, 4, 1, 0, 0);     // conv1 waits before weights
    run_stage(ox2, 128, 128, 4, ox4, 4, 1, 0, 1);
    run_stage(ox4, 256, 256, 8, ox8, 4, 1, 0, 1);
    run_stage(ox8, 512, 512, 12, ox16, 4, 1, 0, 1);
    // MSF stage: conv1 computes x16 + up8(x2)+up4(x4)+up2(x8) inline from ox16.
    run_stage(ox16, 1024, 1024, 16, omsf, 1, 0, 1, 1);
}